// round 3
// baseline (speedup 1.0000x reference)
#include <cuda_runtime.h>
#include <math.h>
#include <stdint.h>

// Problem constants
#define BATCH 8
#define CIN   256
#define CH    256
#define HH    128
#define WW    128
#define HW    (HH*WW)          // 16384
#define NPIX  (BATCH*HW)       // 131072
#define KTOT  (CIN*9)          // 2304
#define NGRP  8
#define CPG   32               // channels per group

// Output layout (float32, tuple order, flattened+concatenated)
#define O_DMG   0
#define O_CORN  131072
#define O_PIX   393216
#define O_PRED  917504
#define O_MEAN  1048576
#define O_TOPK  1048608
#define O_AGG   1048640
#define O_AGGL  1048672

// -------- scratch (no cudaMalloc allowed) --------
__device__ float g_hd[(size_t)BATCH*CH*HW];     // damage head conv3x3 out (134MB)
__device__ float g_hs[(size_t)BATCH*CH*HW];     // severity head conv3x3 out
__device__ float g_stats[2*BATCH*NGRP*2];       // (head,b,g) -> mu, rsig
__device__ float g_mean_raw[BATCH*4];
__device__ float g_topk_raw[BATCH*4];
__device__ int   g_cnt[BATCH];

// ============================================================
// Kernel 1: conv3x3 (SAME, no bias) as implicit GEMM
// Tile: 64 out-channels x 64 pixels (one row segment), BK=32.
// grid = (2048 pixel tiles, 4 co tiles, 2 heads), 256 threads.
// ============================================================
__global__ __launch_bounds__(256) void conv3x3_kernel(
    const float* __restrict__ in,
    const float* __restrict__ wd,
    const float* __restrict__ ws)
{
    const float* __restrict__ wgt = blockIdx.z ? ws : wd;
    float* __restrict__ out       = blockIdx.z ? g_hs : g_hd;

    __shared__ float As[32][64];   // [kk][co]
    __shared__ float Bs[32][64];   // [kk][px]

    const int pbase = blockIdx.x * 64;
    const int n     = pbase >> 14;         // /16384
    const int rem   = pbase & 16383;
    const int y     = rem >> 7;
    const int x0    = rem & 127;           // 0 or 64
    const int co0   = blockIdx.y * 64;

    const int tid = threadIdx.x;
    const int tx  = tid & 15;
    const int ty  = tid >> 4;

    // Load-phase thread mapping
    const int a_col = tid >> 2;            // 0..63
    const int a_kk0 = (tid & 3) * 8;       // 0,8,16,24
    const int b_kk  = tid >> 3;            // 0..31
    const int b_pp0 = (tid & 7) * 8;       // 0..56

    const float* __restrict__ inb = in + (size_t)n * CIN * HW;

    float acc[4][4];
#pragma unroll
    for (int i = 0; i < 4; i++)
#pragma unroll
        for (int j = 0; j < 4; j++) acc[i][j] = 0.f;

    for (int k0 = 0; k0 < KTOT; k0 += 32) {
        // ---- load As (weights): wgt[(co0+col)*K + k0+kk] ----
        const float* wrow = wgt + (size_t)(co0 + a_col) * KTOT + k0 + a_kk0;
#pragma unroll
        for (int j = 0; j < 8; j++)
            As[a_kk0 + j][a_col] = wrow[j];

        // ---- load Bs (im2col on the fly) ----
        {
            const int k  = k0 + b_kk;
            const int ci = k / 9;
            const int rs = k - ci * 9;
            const int r  = rs / 3;
            const int s  = rs - r * 3;
            const int yy = y + r - 1;
            const int xb = x0 + s - 1 + b_pp0;
            const float* irow = inb + (size_t)ci * HW + yy * WW;
            const bool yok = ((unsigned)yy < (unsigned)HH);
#pragma unroll
            for (int j = 0; j < 8; j++) {
                const int xx = xb + j;
                float v = 0.f;
                if (yok && ((unsigned)xx < (unsigned)WW)) v = irow[xx];
                Bs[b_kk][b_pp0 + j] = v;
            }
        }
        __syncthreads();

#pragma unroll
        for (int kk = 0; kk < 32; kk++) {
            const float4 a = *(const float4*)(&As[kk][ty << 2]);
            const float4 b = *(const float4*)(&Bs[kk][tx << 2]);
            acc[0][0] = fmaf(a.x, b.x, acc[0][0]);
            acc[0][1] = fmaf(a.x, b.y, acc[0][1]);
            acc[0][2] = fmaf(a.x, b.z, acc[0][2]);
            acc[0][3] = fmaf(a.x, b.w, acc[0][3]);
            acc[1][0] = fmaf(a.y, b.x, acc[1][0]);
            acc[1][1] = fmaf(a.y, b.y, acc[1][1]);
            acc[1][2] = fmaf(a.y, b.z, acc[1][2]);
            acc[1][3] = fmaf(a.y, b.w, acc[1][3]);
            acc[2][0] = fmaf(a.z, b.x, acc[2][0]);
            acc[2][1] = fmaf(a.z, b.y, acc[2][1]);
            acc[2][2] = fmaf(a.z, b.z, acc[2][2]);
            acc[2][3] = fmaf(a.z, b.w, acc[2][3]);
            acc[3][0] = fmaf(a.w, b.x, acc[3][0]);
            acc[3][1] = fmaf(a.w, b.y, acc[3][1]);
            acc[3][2] = fmaf(a.w, b.z, acc[3][2]);
            acc[3][3] = fmaf(a.w, b.w, acc[3][3]);
        }
        __syncthreads();
    }

    // ---- store: out[n, co, y, x] ----
    float* ob = out + ((size_t)n * CH + co0) * HW + rem + (tx << 2);
#pragma unroll
    for (int i = 0; i < 4; i++) {
        const int co = (ty << 2) + i;
        float4 v = make_float4(acc[i][0], acc[i][1], acc[i][2], acc[i][3]);
        *(float4*)(ob + (size_t)co * HW) = v;
    }
}

// ============================================================
// Kernel 2: GroupNorm stats. grid = (group, batch, head), 256 thr.
// Reduces contiguous 32*16384 floats. Deterministic tree reduce.
// ============================================================
__global__ __launch_bounds__(256) void gn_stats_kernel()
{
    const float* h = blockIdx.z ? g_hs : g_hd;
    const float* p = h + ((size_t)blockIdx.y * CH + blockIdx.x * CPG) * HW;
    const int n = CPG * HW; // 524288
    const int tid = threadIdx.x;

    float s = 0.f, s2 = 0.f;
    for (int i = tid; i < n; i += 256) {
        float v = p[i];
        s += v;
        s2 = fmaf(v, v, s2);
    }
    __shared__ float sh[256], sh2[256];
    sh[tid] = s; sh2[tid] = s2;
    __syncthreads();
    for (int off = 128; off > 0; off >>= 1) {
        if (tid < off) { sh[tid] += sh[tid + off]; sh2[tid] += sh2[tid + off]; }
        __syncthreads();
    }
    if (tid == 0) {
        float mu  = sh[0] / (float)n;
        float var = sh2[0] / (float)n - mu * mu;
        float rs  = rsqrtf(var + 1e-5f);
        int idx = ((blockIdx.z * BATCH + blockIdx.y) * NGRP + blockIdx.x) * 2;
        g_stats[idx]     = mu;
        g_stats[idx + 1] = rs;
    }
}

// ============================================================
// Kernel 3: per-pixel epilogue. GN affine + exact GELU + 1x1 convs
// + sigmoid/CORN decode/normalize/labels. grid = 512, 256 thr.
// ============================================================
__global__ __launch_bounds__(256) void epilogue_kernel(
    const float* __restrict__ dgs, const float* __restrict__ dgb,
    const float* __restrict__ dw2, const float* __restrict__ db2,
    const float* __restrict__ sgs, const float* __restrict__ sgb,
    const float* __restrict__ sw2, const float* __restrict__ sb2,
    float* __restrict__ out)
{
    __shared__ float s_dgs[CH], s_dgb[CH], s_dw2[CH];
    __shared__ float s_sgs[CH], s_sgb[CH], s_sw0[CH], s_sw1[CH];
    __shared__ float s_mu[2][NGRP], s_rs[2][NGRP];

    const int tid = threadIdx.x;
    const int p   = blockIdx.x * 256 + tid;
    const int n   = p >> 14;
    const int pix = p & 16383;

    for (int c = tid; c < CH; c += 256) {
        s_dgs[c] = dgs[c]; s_dgb[c] = dgb[c]; s_dw2[c] = dw2[c];
        s_sgs[c] = sgs[c]; s_sgb[c] = sgb[c];
        s_sw0[c] = sw2[c]; s_sw1[c] = sw2[CH + c];
    }
    if (tid < 16) {
        int h = tid >> 3, g = tid & 7;
        int idx = ((h * BATCH + n) * NGRP + g) * 2;
        s_mu[h][g] = g_stats[idx];
        s_rs[h][g] = g_stats[idx + 1];
    }
    __syncthreads();

    const float* hd = g_hd + (size_t)n * CH * HW + pix;
    const float* hs = g_hs + (size_t)n * CH * HW + pix;

    float dl = 0.f, sl0 = 0.f, sl1 = 0.f;
#pragma unroll 4
    for (int c = 0; c < CH; c++) {
        const int g = c >> 5;
        float v  = hd[(size_t)c * HW];
        float xn = fmaf((v - s_mu[0][g]) * s_rs[0][g], s_dgs[c], s_dgb[c]);
        float ge = xn * normcdff(xn);                 // exact GELU
        dl = fmaf(ge, s_dw2[c], dl);

        v  = hs[(size_t)c * HW];
        xn = fmaf((v - s_mu[1][g]) * s_rs[1][g], s_sgs[c], s_sgb[c]);
        ge = xn * normcdff(xn);
        sl0 = fmaf(ge, s_sw0[c], sl0);
        sl1 = fmaf(ge, s_sw1[c], sl1);
    }
    dl  += db2[0];
    sl0 += sb2[0];
    sl1 += sb2[1];

    // CORN decode
    const float pd = 1.f / (1.f + expf(-dl));
    const float t0 = 1.f / (1.f + expf(-sl0));
    const float t1 = t0 * (1.f / (1.f + expf(-sl1)));
    float sev0 = fmaxf(1.f - t0, 1e-8f);
    float sev1 = fmaxf(t0 - t1, 1e-8f);
    float sev2 = fmaxf(t1,       1e-8f);
    const float ssum = fmaxf(sev0 + sev1 + sev2, 1e-8f);
    sev0 /= ssum; sev1 /= ssum; sev2 /= ssum;

    float px0 = fmaxf(1.f - pd,   1e-8f);
    float px1 = fmaxf(pd * sev0,  1e-8f);
    float px2 = fmaxf(pd * sev1,  1e-8f);
    float px3 = fmaxf(pd * sev2,  1e-8f);
    const float psum = fmaxf(px0 + px1 + px2 + px3, 1e-8f);
    px0 /= psum; px1 /= psum; px2 /= psum; px3 /= psum;

    int sp = 0; float bm = sev0;
    if (sev1 > bm) { bm = sev1; sp = 1; }
    if (sev2 > bm) { bm = sev2; sp = 2; }
    const int lbl = (pd >= 0.5f) ? (sp + 1) : 0;

    out[O_DMG  + n * HW + pix]            = dl;
    out[O_CORN + (n * 2 + 0) * HW + pix]  = sl0;
    out[O_CORN + (n * 2 + 1) * HW + pix]  = sl1;
    out[O_PIX  + (n * 4 + 0) * HW + pix]  = px0;
    out[O_PIX  + (n * 4 + 1) * HW + pix]  = px1;
    out[O_PIX  + (n * 4 + 2) * HW + pix]  = px2;
    out[O_PIX  + (n * 4 + 3) * HW + pix]  = px3;
    out[O_PRED + n * HW + pix]            = (float)lbl;
}

// ============================================================
// Kernel 4: masked mean + exact top-k sum per (b,c). 32 blocks.
// Bitwise max-threshold select on positive float bit patterns
// gives the exact k-th largest value (ties handled like sorted cumsum).
// ============================================================
__global__ __launch_bounds__(256) void reduce_topk_kernel(
    const float* __restrict__ mask, const float* __restrict__ pix)
{
    extern __shared__ unsigned skey[];   // 16384 keys
    __shared__ int   ibuf[256];
    __shared__ float fbuf[256];

    const int tid = threadIdx.x;
    const int b = blockIdx.x >> 2;
    const int c = blockIdx.x & 3;
    const float* pv = pix  + ((size_t)b * 4 + c) * HW;
    const float* mk = mask + (size_t)b * HW;

    for (int i = tid; i < HW; i += 256)
        skey[i] = (mk[i] > 0.5f) ? __float_as_uint(pv[i]) : 0u;   // valid values are > 0
    __syncthreads();

    // cnt (valid count) and masked sum — deterministic tree
    int   mc = 0;
    float ms = 0.f;
    for (int i = tid; i < HW; i += 256) {
        unsigned kk = skey[i];
        if (kk) { mc++; ms += __uint_as_float(kk); }
    }
    ibuf[tid] = mc; fbuf[tid] = ms;
    __syncthreads();
    for (int off = 128; off > 0; off >>= 1) {
        if (tid < off) { ibuf[tid] += ibuf[tid + off]; fbuf[tid] += fbuf[tid + off]; }
        __syncthreads();
    }
    const int   cnt    = ibuf[0];
    const float sumall = fbuf[0];
    __syncthreads();

    // k = clip(rint(cnt*0.2), 1, max(cnt,1))  (rintf == banker's rounding == jnp.round)
    int k = (int)rintf((float)cnt * 0.2f);
    if (k < 1) k = 1;
    const int cmax = (cnt > 1) ? cnt : 1;
    if (k > cmax) k = cmax;

    // exact k-th largest via 31-bit greedy descent (monotone predicate)
    unsigned prefix = 0u;
    for (int bit = 30; bit >= 0; bit--) {
        const unsigned cand = prefix | (1u << bit);
        int cl = 0;
        for (int i = tid; i < HW; i += 256)
            if (skey[i] >= cand) cl++;
        ibuf[tid] = cl;
        __syncthreads();
        for (int off = 128; off > 0; off >>= 1) {
            if (tid < off) ibuf[tid] += ibuf[tid + off];
            __syncthreads();
        }
        if (ibuf[0] >= k) prefix = cand;
        __syncthreads();
    }

    // sum of elements strictly above threshold, plus tie fill-in
    int   cg = 0;
    float sg = 0.f;
    for (int i = tid; i < HW; i += 256) {
        unsigned kk = skey[i];
        if (kk > prefix) { cg++; sg += __uint_as_float(kk); }
    }
    ibuf[tid] = cg; fbuf[tid] = sg;
    __syncthreads();
    for (int off = 128; off > 0; off >>= 1) {
        if (tid < off) { ibuf[tid] += ibuf[tid + off]; fbuf[tid] += fbuf[tid + off]; }
        __syncthreads();
    }
    if (tid == 0) {
        const float T = __uint_as_float(prefix);
        const float topsum = fbuf[0] + (float)(k - ibuf[0]) * T;
        g_mean_raw[b * 4 + c] = sumall / (float)((cnt > 1) ? cnt : 1);
        g_topk_raw[b * 4 + c] = topsum / (float)k;
        g_cnt[b] = cnt;
    }
}

// ============================================================
// Kernel 5: finalize mean_p / topk_p / agg / agg_labels
// ============================================================
__global__ void finalize_kernel(float* __restrict__ out)
{
    const int b = threadIdx.x;
    if (b >= BATCH) return;
    const int cnt = g_cnt[b];

    float m[4], t[4], a[4];
    float sm = 0.f, st = 0.f;
    for (int c = 0; c < 4; c++) {
        m[c] = (cnt == 0) ? 0.25f : fmaxf(g_mean_raw[b * 4 + c], 1e-8f);
        t[c] = (cnt == 0) ? 0.25f : fmaxf(g_topk_raw[b * 4 + c], 1e-8f);
        sm += m[c]; st += t[c];
    }
    sm = fmaxf(sm, 1e-8f); st = fmaxf(st, 1e-8f);
    float sa = 0.f;
    for (int c = 0; c < 4; c++) {
        m[c] /= sm; t[c] /= st;
        a[c] = fmaxf(0.7f * m[c] + 0.3f * t[c], 1e-8f);
        sa += a[c];
    }
    sa = fmaxf(sa, 1e-8f);
    int best = 0; float bv = -1.f;
    for (int c = 0; c < 4; c++) {
        a[c] /= sa;
        if (a[c] > bv) { bv = a[c]; best = c; }
        out[O_MEAN + b * 4 + c] = m[c];
        out[O_TOPK + b * 4 + c] = t[c];
        out[O_AGG  + b * 4 + c] = a[c];
    }
    out[O_AGGL + b] = (float)best;
}

// ============================================================
extern "C" void kernel_launch(void* const* d_in, const int* in_sizes, int n_in,
                              void* d_out, int out_size)
{
    const float* fm   = (const float*)d_in[0];
    const float* mask = (const float*)d_in[1];
    const float* dw1  = (const float*)d_in[2];
    const float* dgs  = (const float*)d_in[3];
    const float* dgb  = (const float*)d_in[4];
    const float* dw2  = (const float*)d_in[5];
    const float* db2  = (const float*)d_in[6];
    const float* sw1  = (const float*)d_in[7];
    const float* sgs  = (const float*)d_in[8];
    const float* sgb  = (const float*)d_in[9];
    const float* sw2  = (const float*)d_in[10];
    const float* sb2  = (const float*)d_in[11];
    float* out = (float*)d_out;

    cudaFuncSetAttribute(reduce_topk_kernel,
                         cudaFuncAttributeMaxDynamicSharedMemorySize, HW * 4);

    conv3x3_kernel<<<dim3(NPIX / 64, CH / 64, 2), 256>>>(fm, dw1, sw1);
    gn_stats_kernel<<<dim3(NGRP, BATCH, 2), 256>>>();
    epilogue_kernel<<<NPIX / 256, 256>>>(dgs, dgb, dw2, db2, sgs, sgb, sw2, sb2, out);
    reduce_topk_kernel<<<BATCH * 4, 256, HW * 4>>>(mask, out + O_PIX);
    finalize_kernel<<<1, 32>>>(out);
}

// round 4
// speedup vs baseline: 1.6385x; 1.6385x over previous
#include <cuda_runtime.h>
#include <math.h>
#include <stdint.h>

// Problem constants
#define BATCH 8
#define CIN   256
#define CH    256
#define HH    128
#define WW    128
#define HW    (HH*WW)          // 16384
#define NPIX  (BATCH*HW)       // 131072
#define KTOT  (CIN*9)          // 2304
#define NGRP  8
#define CPG   32               // channels per group

// Output layout (float32, tuple order, flattened+concatenated)
#define O_DMG   0
#define O_CORN  131072
#define O_PIX   393216
#define O_PRED  917504
#define O_MEAN  1048576
#define O_TOPK  1048608
#define O_AGG   1048640
#define O_AGGL  1048672

// -------- scratch (no cudaMalloc allowed) --------
__device__ float g_hd[(size_t)BATCH*CH*HW];     // damage head conv3x3 out (134MB)
__device__ float g_hs[(size_t)BATCH*CH*HW];     // severity head conv3x3 out
__device__ float g_stats[2*BATCH*NGRP*2];       // (head,b,g) -> mu, rsig
__device__ float g_mean_raw[BATCH*4];
__device__ float g_topk_raw[BATCH*4];
__device__ int   g_cnt[BATCH];

// ============================================================
// Kernel 1: conv3x3 (SAME, no bias) as implicit GEMM
// Tile: 64 out-channels x 64 pixels (one row segment), BK=32.
// grid = (2048 pixel tiles, 4 co tiles, 2 heads), 256 threads.
// ============================================================
__global__ __launch_bounds__(256) void conv3x3_kernel(
    const float* __restrict__ in,
    const float* __restrict__ wd,
    const float* __restrict__ ws)
{
    const float* __restrict__ wgt = blockIdx.z ? ws : wd;
    float* __restrict__ out       = blockIdx.z ? g_hs : g_hd;

    __shared__ float As[32][64];   // [kk][co]
    __shared__ float Bs[32][64];   // [kk][px]

    const int pbase = blockIdx.x * 64;
    const int n     = pbase >> 14;         // /16384
    const int rem   = pbase & 16383;
    const int y     = rem >> 7;
    const int x0    = rem & 127;           // 0 or 64
    const int co0   = blockIdx.y * 64;

    const int tid = threadIdx.x;
    const int tx  = tid & 15;
    const int ty  = tid >> 4;

    // Load-phase thread mapping
    const int a_col = tid >> 2;            // 0..63
    const int a_kk0 = (tid & 3) * 8;       // 0,8,16,24
    const int b_kk  = tid >> 3;            // 0..31
    const int b_pp0 = (tid & 7) * 8;       // 0..56

    const float* __restrict__ inb = in + (size_t)n * CIN * HW;

    float acc[4][4];
#pragma unroll
    for (int i = 0; i < 4; i++)
#pragma unroll
        for (int j = 0; j < 4; j++) acc[i][j] = 0.f;

    for (int k0 = 0; k0 < KTOT; k0 += 32) {
        // ---- load As (weights): wgt[(co0+col)*K + k0+kk] ----
        const float* wrow = wgt + (size_t)(co0 + a_col) * KTOT + k0 + a_kk0;
#pragma unroll
        for (int j = 0; j < 8; j++)
            As[a_kk0 + j][a_col] = wrow[j];

        // ---- load Bs (im2col on the fly) ----
        {
            const int k  = k0 + b_kk;
            const int ci = k / 9;
            const int rs = k - ci * 9;
            const int r  = rs / 3;
            const int s  = rs - r * 3;
            const int yy = y + r - 1;
            const int xb = x0 + s - 1 + b_pp0;
            const float* irow = inb + (size_t)ci * HW + yy * WW;
            const bool yok = ((unsigned)yy < (unsigned)HH);
#pragma unroll
            for (int j = 0; j < 8; j++) {
                const int xx = xb + j;
                float v = 0.f;
                if (yok && ((unsigned)xx < (unsigned)WW)) v = irow[xx];
                Bs[b_kk][b_pp0 + j] = v;
            }
        }
        __syncthreads();

#pragma unroll
        for (int kk = 0; kk < 32; kk++) {
            const float4 a = *(const float4*)(&As[kk][ty << 2]);
            const float4 b = *(const float4*)(&Bs[kk][tx << 2]);
            acc[0][0] = fmaf(a.x, b.x, acc[0][0]);
            acc[0][1] = fmaf(a.x, b.y, acc[0][1]);
            acc[0][2] = fmaf(a.x, b.z, acc[0][2]);
            acc[0][3] = fmaf(a.x, b.w, acc[0][3]);
            acc[1][0] = fmaf(a.y, b.x, acc[1][0]);
            acc[1][1] = fmaf(a.y, b.y, acc[1][1]);
            acc[1][2] = fmaf(a.y, b.z, acc[1][2]);
            acc[1][3] = fmaf(a.y, b.w, acc[1][3]);
            acc[2][0] = fmaf(a.z, b.x, acc[2][0]);
            acc[2][1] = fmaf(a.z, b.y, acc[2][1]);
            acc[2][2] = fmaf(a.z, b.z, acc[2][2]);
            acc[2][3] = fmaf(a.z, b.w, acc[2][3]);
            acc[3][0] = fmaf(a.w, b.x, acc[3][0]);
            acc[3][1] = fmaf(a.w, b.y, acc[3][1]);
            acc[3][2] = fmaf(a.w, b.z, acc[3][2]);
            acc[3][3] = fmaf(a.w, b.w, acc[3][3]);
        }
        __syncthreads();
    }

    // ---- store: out[n, co, y, x] ----
    float* ob = out + ((size_t)n * CH + co0) * HW + rem + (tx << 2);
#pragma unroll
    for (int i = 0; i < 4; i++) {
        const int co = (ty << 2) + i;
        float4 v = make_float4(acc[i][0], acc[i][1], acc[i][2], acc[i][3]);
        *(float4*)(ob + (size_t)co * HW) = v;
    }
}

// ============================================================
// Kernel 2: GroupNorm stats. grid = (group, batch, head), 256 thr.
// Reduces contiguous 32*16384 floats. Deterministic tree reduce.
// ============================================================
__global__ __launch_bounds__(256) void gn_stats_kernel()
{
    const float* h = blockIdx.z ? g_hs : g_hd;
    const float* p = h + ((size_t)blockIdx.y * CH + blockIdx.x * CPG) * HW;
    const int n = CPG * HW; // 524288
    const int tid = threadIdx.x;

    float s = 0.f, s2 = 0.f;
    for (int i = tid; i < n; i += 256) {
        float v = p[i];
        s += v;
        s2 = fmaf(v, v, s2);
    }
    __shared__ float sh[256], sh2[256];
    sh[tid] = s; sh2[tid] = s2;
    __syncthreads();
    for (int off = 128; off > 0; off >>= 1) {
        if (tid < off) { sh[tid] += sh[tid + off]; sh2[tid] += sh2[tid + off]; }
        __syncthreads();
    }
    if (tid == 0) {
        float mu  = sh[0] / (float)n;
        float var = sh2[0] / (float)n - mu * mu;
        float rs  = rsqrtf(var + 1e-5f);
        int idx = ((blockIdx.z * BATCH + blockIdx.y) * NGRP + blockIdx.x) * 2;
        g_stats[idx]     = mu;
        g_stats[idx + 1] = rs;
    }
}

// ============================================================
// Kernel 3: per-pixel epilogue. GN affine + exact GELU + 1x1 convs
// + sigmoid/CORN decode/normalize/labels. grid = 512, 256 thr.
// ============================================================
__global__ __launch_bounds__(256) void epilogue_kernel(
    const float* __restrict__ dgs, const float* __restrict__ dgb,
    const float* __restrict__ dw2, const float* __restrict__ db2,
    const float* __restrict__ sgs, const float* __restrict__ sgb,
    const float* __restrict__ sw2, const float* __restrict__ sb2,
    float* __restrict__ out)
{
    __shared__ float s_dgs[CH], s_dgb[CH], s_dw2[CH];
    __shared__ float s_sgs[CH], s_sgb[CH], s_sw0[CH], s_sw1[CH];
    __shared__ float s_mu[2][NGRP], s_rs[2][NGRP];

    const int tid = threadIdx.x;
    const int p   = blockIdx.x * 256 + tid;
    const int n   = p >> 14;
    const int pix = p & 16383;

    for (int c = tid; c < CH; c += 256) {
        s_dgs[c] = dgs[c]; s_dgb[c] = dgb[c]; s_dw2[c] = dw2[c];
        s_sgs[c] = sgs[c]; s_sgb[c] = sgb[c];
        s_sw0[c] = sw2[c]; s_sw1[c] = sw2[CH + c];
    }
    if (tid < 16) {
        int h = tid >> 3, g = tid & 7;
        int idx = ((h * BATCH + n) * NGRP + g) * 2;
        s_mu[h][g] = g_stats[idx];
        s_rs[h][g] = g_stats[idx + 1];
    }
    __syncthreads();

    const float* hd = g_hd + (size_t)n * CH * HW + pix;
    const float* hs = g_hs + (size_t)n * CH * HW + pix;

    float dl = 0.f, sl0 = 0.f, sl1 = 0.f;
#pragma unroll 4
    for (int c = 0; c < CH; c++) {
        const int g = c >> 5;
        float v  = hd[(size_t)c * HW];
        float xn = fmaf((v - s_mu[0][g]) * s_rs[0][g], s_dgs[c], s_dgb[c]);
        float ge = xn * normcdff(xn);                 // exact GELU
        dl = fmaf(ge, s_dw2[c], dl);

        v  = hs[(size_t)c * HW];
        xn = fmaf((v - s_mu[1][g]) * s_rs[1][g], s_sgs[c], s_sgb[c]);
        ge = xn * normcdff(xn);
        sl0 = fmaf(ge, s_sw0[c], sl0);
        sl1 = fmaf(ge, s_sw1[c], sl1);
    }
    dl  += db2[0];
    sl0 += sb2[0];
    sl1 += sb2[1];

    // CORN decode
    const float pd = 1.f / (1.f + expf(-dl));
    const float t0 = 1.f / (1.f + expf(-sl0));
    const float t1 = t0 * (1.f / (1.f + expf(-sl1)));
    float sev0 = fmaxf(1.f - t0, 1e-8f);
    float sev1 = fmaxf(t0 - t1, 1e-8f);
    float sev2 = fmaxf(t1,       1e-8f);
    const float ssum = fmaxf(sev0 + sev1 + sev2, 1e-8f);
    sev0 /= ssum; sev1 /= ssum; sev2 /= ssum;

    float px0 = fmaxf(1.f - pd,   1e-8f);
    float px1 = fmaxf(pd * sev0,  1e-8f);
    float px2 = fmaxf(pd * sev1,  1e-8f);
    float px3 = fmaxf(pd * sev2,  1e-8f);
    const float psum = fmaxf(px0 + px1 + px2 + px3, 1e-8f);
    px0 /= psum; px1 /= psum; px2 /= psum; px3 /= psum;

    int sp = 0; float bm = sev0;
    if (sev1 > bm) { bm = sev1; sp = 1; }
    if (sev2 > bm) { bm = sev2; sp = 2; }
    const int lbl = (pd >= 0.5f) ? (sp + 1) : 0;

    out[O_DMG  + n * HW + pix]            = dl;
    out[O_CORN + (n * 2 + 0) * HW + pix]  = sl0;
    out[O_CORN + (n * 2 + 1) * HW + pix]  = sl1;
    out[O_PIX  + (n * 4 + 0) * HW + pix]  = px0;
    out[O_PIX  + (n * 4 + 1) * HW + pix]  = px1;
    out[O_PIX  + (n * 4 + 2) * HW + pix]  = px2;
    out[O_PIX  + (n * 4 + 3) * HW + pix]  = px3;
    out[O_PRED + n * HW + pix]            = (float)lbl;
}

// ============================================================
// Kernel 4: masked mean + exact top-k sum per (b,c). 32 blocks.
// Bitwise max-threshold select on positive float bit patterns
// gives the exact k-th largest value (ties handled like sorted cumsum).
// ============================================================
__global__ __launch_bounds__(256) void reduce_topk_kernel(
    const float* __restrict__ mask, const float* __restrict__ pix)
{
    extern __shared__ unsigned skey[];   // 16384 keys
    __shared__ int   ibuf[256];
    __shared__ float fbuf[256];

    const int tid = threadIdx.x;
    const int b = blockIdx.x >> 2;
    const int c = blockIdx.x & 3;
    const float* pv = pix  + ((size_t)b * 4 + c) * HW;
    const float* mk = mask + (size_t)b * HW;

    for (int i = tid; i < HW; i += 256)
        skey[i] = (mk[i] > 0.5f) ? __float_as_uint(pv[i]) : 0u;   // valid values are > 0
    __syncthreads();

    // cnt (valid count) and masked sum — deterministic tree
    int   mc = 0;
    float ms = 0.f;
    for (int i = tid; i < HW; i += 256) {
        unsigned kk = skey[i];
        if (kk) { mc++; ms += __uint_as_float(kk); }
    }
    ibuf[tid] = mc; fbuf[tid] = ms;
    __syncthreads();
    for (int off = 128; off > 0; off >>= 1) {
        if (tid < off) { ibuf[tid] += ibuf[tid + off]; fbuf[tid] += fbuf[tid + off]; }
        __syncthreads();
    }
    const int   cnt    = ibuf[0];
    const float sumall = fbuf[0];
    __syncthreads();

    // k = clip(rint(cnt*0.2), 1, max(cnt,1))  (rintf == banker's rounding == jnp.round)
    int k = (int)rintf((float)cnt * 0.2f);
    if (k < 1) k = 1;
    const int cmax = (cnt > 1) ? cnt : 1;
    if (k > cmax) k = cmax;

    // exact k-th largest via 31-bit greedy descent (monotone predicate)
    unsigned prefix = 0u;
    for (int bit = 30; bit >= 0; bit--) {
        const unsigned cand = prefix | (1u << bit);
        int cl = 0;
        for (int i = tid; i < HW; i += 256)
            if (skey[i] >= cand) cl++;
        ibuf[tid] = cl;
        __syncthreads();
        for (int off = 128; off > 0; off >>= 1) {
            if (tid < off) ibuf[tid] += ibuf[tid + off];
            __syncthreads();
        }
        if (ibuf[0] >= k) prefix = cand;
        __syncthreads();
    }

    // sum of elements strictly above threshold, plus tie fill-in
    int   cg = 0;
    float sg = 0.f;
    for (int i = tid; i < HW; i += 256) {
        unsigned kk = skey[i];
        if (kk > prefix) { cg++; sg += __uint_as_float(kk); }
    }
    ibuf[tid] = cg; fbuf[tid] = sg;
    __syncthreads();
    for (int off = 128; off > 0; off >>= 1) {
        if (tid < off) { ibuf[tid] += ibuf[tid + off]; fbuf[tid] += fbuf[tid + off]; }
        __syncthreads();
    }
    if (tid == 0) {
        const float T = __uint_as_float(prefix);
        const float topsum = fbuf[0] + (float)(k - ibuf[0]) * T;
        g_mean_raw[b * 4 + c] = sumall / (float)((cnt > 1) ? cnt : 1);
        g_topk_raw[b * 4 + c] = topsum / (float)k;
        g_cnt[b] = cnt;
    }
}

// ============================================================
// Kernel 5: finalize mean_p / topk_p / agg / agg_labels
// ============================================================
__global__ void finalize_kernel(float* __restrict__ out)
{
    const int b = threadIdx.x;
    if (b >= BATCH) return;
    const int cnt = g_cnt[b];

    float m[4], t[4], a[4];
    float sm = 0.f, st = 0.f;
    for (int c = 0; c < 4; c++) {
        m[c] = (cnt == 0) ? 0.25f : fmaxf(g_mean_raw[b * 4 + c], 1e-8f);
        t[c] = (cnt == 0) ? 0.25f : fmaxf(g_topk_raw[b * 4 + c], 1e-8f);
        sm += m[c]; st += t[c];
    }
    sm = fmaxf(sm, 1e-8f); st = fmaxf(st, 1e-8f);
    float sa = 0.f;
    for (int c = 0; c < 4; c++) {
        m[c] /= sm; t[c] /= st;
        a[c] = fmaxf(0.7f * m[c] + 0.3f * t[c], 1e-8f);
        sa += a[c];
    }
    sa = fmaxf(sa, 1e-8f);
    int best = 0; float bv = -1.f;
    for (int c = 0; c < 4; c++) {
        a[c] /= sa;
        if (a[c] > bv) { bv = a[c]; best = c; }
        out[O_MEAN + b * 4 + c] = m[c];
        out[O_TOPK + b * 4 + c] = t[c];
        out[O_AGG  + b * 4 + c] = a[c];
    }
    out[O_AGGL + b] = (float)best;
}

// ============================================================
extern "C" void kernel_launch(void* const* d_in, const int* in_sizes, int n_in,
                              void* d_out, int out_size)
{
    const float* fm   = (const float*)d_in[0];
    const float* mask = (const float*)d_in[1];
    const float* dw1  = (const float*)d_in[2];
    const float* dgs  = (const float*)d_in[3];
    const float* dgb  = (const float*)d_in[4];
    const float* dw2  = (const float*)d_in[5];
    const float* db2  = (const float*)d_in[6];
    const float* sw1  = (const float*)d_in[7];
    const float* sgs  = (const float*)d_in[8];
    const float* sgb  = (const float*)d_in[9];
    const float* sw2  = (const float*)d_in[10];
    const float* sb2  = (const float*)d_in[11];
    float* out = (float*)d_out;

    cudaFuncSetAttribute(reduce_topk_kernel,
                         cudaFuncAttributeMaxDynamicSharedMemorySize, HW * 4);

    conv3x3_kernel<<<dim3(NPIX / 64, CH / 64, 2), 256>>>(fm, dw1, sw1);
    gn_stats_kernel<<<dim3(NGRP, BATCH, 2), 256>>>();
    epilogue_kernel<<<NPIX / 256, 256>>>(dgs, dgb, dw2, db2, sgs, sgb, sw2, sb2, out);
    reduce_topk_kernel<<<BATCH * 4, 256, HW * 4>>>(mask, out + O_PIX);
    finalize_kernel<<<1, 32>>>(out);
}

// round 6
// speedup vs baseline: 4.7453x; 2.8962x over previous
#include <cuda_runtime.h>
#include <math.h>
#include <stdint.h>

// Problem constants
#define BATCH 8
#define CIN   256
#define CH    256
#define HH    128
#define WW    128
#define HW    (HH*WW)          // 16384
#define NPIX  (BATCH*HW)       // 131072
#define NGRP  8
#define CPG   32

// Output layout (float32, tuple order, flattened+concatenated)
#define O_DMG   0
#define O_CORN  131072
#define O_PIX   393216
#define O_PRED  917504
#define O_MEAN  1048576
#define O_TOPK  1048608
#define O_AGG   1048640
#define O_AGGL  1048672

// -------- scratch (no cudaMalloc allowed) --------
__device__ float g_hd[(size_t)BATCH*CH*HW];          // damage conv3x3 out
__device__ float g_hs[(size_t)BATCH*CH*HW];          // severity conv3x3 out
// Weights, frag-permuted: [head][rs(9)][mg(16)][kk(32)][lane(32)] float4
__device__ float4 g_wah[2*9*16*32*32];
__device__ float4 g_wal[2*9*16*32*32];
// Input, frag-permuted, 3 x-shift planes: [s][n][pg(2048)][kk(32)][lane(32)] float2
__device__ float2 g_bah[(size_t)3*BATCH*2048*32*32];
__device__ float2 g_bal[(size_t)3*BATCH*2048*32*32];
__device__ float g_part[2048*2];
__device__ float g_stats[2*BATCH*NGRP*2];
__device__ float g_mean_raw[BATCH*4];
__device__ float g_topk_raw[BATCH*4];
__device__ int   g_cnt[BATCH];

__device__ __forceinline__ float f2tf32(float v) {
    float r;
    asm("cvt.rna.tf32.f32 %0, %1;" : "=f"(r) : "f"(v));
    return r;
}

#define MMA_TF32(c, a, b) \
    asm volatile("mma.sync.aligned.m16n8k8.row.col.f32.tf32.tf32.f32 " \
        "{%0,%1,%2,%3},{%4,%5,%6,%7},{%8,%9},{%0,%1,%2,%3};" \
        : "+f"((c)[0]), "+f"((c)[1]), "+f"((c)[2]), "+f"((c)[3]) \
        : "r"((a).x), "r"((a).y), "r"((a).z), "r"((a).w), "r"((b).x), "r"((b).y))

#define CP_ASYNC16(dst, src) \
    asm volatile("cp.async.cg.shared.global [%0], [%1], 16;" :: "r"(dst), "l"(src) : "memory")
#define CP_ASYNC16P(dst, src, sz) \
    asm volatile("cp.async.cg.shared.global [%0], [%1], 16, %2;" :: "r"(dst), "l"(src), "r"(sz) : "memory")
#define CP_COMMIT()  asm volatile("cp.async.commit_group;" ::: "memory")
#define CP_WAIT1()   asm volatile("cp.async.wait_group 1;" ::: "memory")

// ============================================================
// Kernel 0a: weight split into tf32 hi/lo, frag-permuted.
// grid = (64, 9, 2), 256 thr. k ordering: rs-major, ci within.
// ============================================================
__global__ __launch_bounds__(256) void convert_w_kernel(
    const float* __restrict__ dw1, const float* __restrict__ sw1)
{
    const int i = blockIdx.x * 256 + threadIdx.x;    // 0..16383
    const int mg = i >> 10;
    const int kk = (i >> 5) & 31;
    const int l  = i & 31;
    const int g = l >> 2, tig = l & 3;
    const int head = blockIdx.z, rs = blockIdx.y;
    const int r = rs / 3, s = rs - r * 3;
    const float* w = head ? sw1 : dw1;

    float a[4];
    const int rows[4] = {g, g + 8, g, g + 8};
    const int cols[4] = {tig, tig, tig + 4, tig + 4};
#pragma unroll
    for (int q = 0; q < 4; q++) {
        int co = mg * 16 + rows[q];
        int ci = kk * 8 + cols[q];
        a[q] = w[((co * CIN + ci) * 3 + r) * 3 + s];
    }
    float4 hi, lo;
    hi.x = f2tf32(a[0]); lo.x = f2tf32(a[0] - hi.x);
    hi.y = f2tf32(a[1]); lo.y = f2tf32(a[1] - hi.y);
    hi.z = f2tf32(a[2]); lo.z = f2tf32(a[2] - hi.z);
    hi.w = f2tf32(a[3]); lo.w = f2tf32(a[3] - hi.w);
    const size_t off = (((size_t)(head * 9 + rs) * 16 + mg) * 32 + kk) * 32 + l;
    g_wah[off] = hi;
    g_wal[off] = lo;
}

// ============================================================
// Kernel 0b: input split into tf32 hi/lo, frag-permuted,
// with 3 pre-applied x-shifts (zeros at x edges).
// grid = (8192, 8), 256 thr.
// ============================================================
__global__ __launch_bounds__(256) void convert_in_kernel(const float* __restrict__ in)
{
    const int n = blockIdx.y;
    const int i = blockIdx.x * 256 + threadIdx.x;    // 0..2097151
    const int pg = i >> 10;
    const int kk = (i >> 5) & 31;
    const int l  = i & 31;
    const int g = l >> 2, tig = l & 3;
    const int pix = pg * 8 + g;
    const int x = pix & 127;
    const int c1 = kk * 8 + tig;

    const float* p1 = in + ((size_t)(n * CIN + c1)) * HW + pix;
    const float* p2 = p1 + (size_t)4 * HW;   // channel c1+4

    float v1[3], v2[3];
    v1[0] = (x > 0)   ? p1[-1] : 0.f;
    v1[1] = p1[0];
    v1[2] = (x < 127) ? p1[1]  : 0.f;
    v2[0] = (x > 0)   ? p2[-1] : 0.f;
    v2[1] = p2[0];
    v2[2] = (x < 127) ? p2[1]  : 0.f;

#pragma unroll
    for (int s = 0; s < 3; s++) {
        float h1 = f2tf32(v1[s]), l1 = f2tf32(v1[s] - h1);
        float h2 = f2tf32(v2[s]), l2 = f2tf32(v2[s] - h2);
        const size_t off = (((size_t)(s * BATCH + n) * 2048 + pg) * 32 + kk) * 32 + l;
        g_bah[off] = make_float2(h1, h2);
        g_bal[off] = make_float2(l1, l2);
    }
}

// ============================================================
// Kernel 1: conv3x3 via 3xTF32 mma.sync implicit GEMM.
// CTA = 128co x 256px, 8 warps (2m x 4n) of 64x64.
// 288 k8 steps (9 rs x 32 kk), stage = 4 kk, 2-stage cp.async.
// grid = dim3(4, 512); blockIdx.x = head*2+cotile (B-sharing adjacent).
// ============================================================
#define STAGE_BYTES 98304   // Ah 16K | Al 16K | Bh 32K | Bl 32K
#define A_LO_OFF 16384
#define B_HI_OFF 32768
#define B_LO_OFF 65536

__device__ __forceinline__ void stage_load(
    char* sp, int st, int head, int cotile, int sn_base, int pg0, int tid)
{
    const int rs  = st >> 3;
    const int kk0 = (st & 7) * 4;
    const int r = rs / 3, s = rs - r * 3;

    // A chunks: 2048 float4 (hi+lo), 8 per thread
    const size_t abase = (((size_t)(head * 9 + rs) * 16 + cotile * 8) * 32 + kk0) * 32;
#pragma unroll
    for (int it = 0; it < 8; it++) {
        const int cid = tid + it * 256;
        const int prec = cid >> 10, cc = cid & 1023;
        const int mgl = cc >> 7, kkl = (cc >> 5) & 3, ll = cc & 31;
        const float4* src = (prec ? g_wal : g_wah) + abase + mgl * 1024 + kkl * 32 + ll;
        uint32_t dst = (uint32_t)__cvta_generic_to_shared(
            sp + prec * A_LO_OFF + ((mgl * 4 + kkl) * 32 + ll) * 16);
        CP_ASYNC16(dst, src);
    }
    // B chunks: 4096 x 16B (hi+lo), 16 per thread; per-pg row-shift predicate
    const size_t bbase = ((size_t)(s * BATCH + sn_base)) * 2048;
    const int pgsh = pg0 + (r - 1) * 16;
#pragma unroll
    for (int it = 0; it < 16; it++) {
        const int cid = tid + it * 256;
        const int prec = cid >> 11, cc = cid & 2047;
        const int pgl = cc >> 6, kkl = (cc >> 4) & 3, lp = cc & 15;
        const int pgsrc = pgsh + pgl;
        const unsigned ok = ((unsigned)pgsrc < 2048u);
        const int pgc = ok ? pgsrc : 0;
        const float2* src = (prec ? g_bal : g_bah)
            + (((bbase + pgc) * 32 + kk0 + kkl) * 32 + lp * 2);
        uint32_t dst = (uint32_t)__cvta_generic_to_shared(
            sp + B_HI_OFF + prec * 32768 + ((pgl * 4 + kkl) * 32 + lp * 2) * 8);
        CP_ASYNC16P(dst, src, ok ? 16u : 0u);
    }
}

__global__ __launch_bounds__(256, 1) void conv_tf32_kernel()
{
    extern __shared__ char smem[];
    const int tid = threadIdx.x;
    const int lane = tid & 31;
    const int wid = tid >> 5;
    const int warp_m = wid >> 2;       // 0..1
    const int warp_n = wid & 3;        // 0..3
    const int g = lane >> 2, tig = lane & 3;

    const int head   = blockIdx.x >> 1;
    const int cotile = blockIdx.x & 1;
    const int ptile  = blockIdx.y;     // 0..511
    const int n      = ptile >> 6;     // 64 tiles per image
    const int pix0   = (ptile & 63) * 256;
    const int pg0    = (ptile & 63) * 32;

    float c[4][8][4];
#pragma unroll
    for (int m = 0; m < 4; m++)
#pragma unroll
        for (int nn = 0; nn < 8; nn++)
#pragma unroll
            for (int q = 0; q < 4; q++) c[m][nn][q] = 0.f;

    char* buf0 = smem;
    char* buf1 = smem + STAGE_BYTES;

    stage_load(buf0, 0, head, cotile, n, pg0, tid); CP_COMMIT();
    stage_load(buf1, 1, head, cotile, n, pg0, tid); CP_COMMIT();

    for (int st = 0; st < 72; st++) {
        CP_WAIT1();
        __syncthreads();
        char* sp = (st & 1) ? buf1 : buf0;

#pragma unroll
        for (int kkl = 0; kkl < 4; kkl++) {
            uint4 Ah[4], Al[4];
#pragma unroll
            for (int m = 0; m < 4; m++) {
                const int mgl = warp_m * 4 + m;
                Ah[m] = *(const uint4*)(sp + ((mgl * 4 + kkl) * 32 + lane) * 16);
                Al[m] = *(const uint4*)(sp + A_LO_OFF + ((mgl * 4 + kkl) * 32 + lane) * 16);
            }
#pragma unroll
            for (int n8 = 0; n8 < 8; n8++) {
                const int pgl = warp_n * 8 + n8;
                uint2 bh = *(const uint2*)(sp + B_HI_OFF + ((pgl * 4 + kkl) * 32 + lane) * 8);
                uint2 bl = *(const uint2*)(sp + B_LO_OFF + ((pgl * 4 + kkl) * 32 + lane) * 8);
#pragma unroll
                for (int m = 0; m < 4; m++) {
                    MMA_TF32(c[m][n8], Ah[m], bh);
                    MMA_TF32(c[m][n8], Al[m], bh);
                    MMA_TF32(c[m][n8], Ah[m], bl);
                }
            }
        }
        __syncthreads();
        if (st + 2 < 72)
            stage_load((st & 1) ? buf1 : buf0, st + 2, head, cotile, n, pg0, tid);
        CP_COMMIT();
    }

    // store to g_hd / g_hs [n][co][pix]
    float* outb = head ? g_hs : g_hd;
#pragma unroll
    for (int m = 0; m < 4; m++) {
        const int co = cotile * 128 + warp_m * 64 + m * 16 + g;
        float* orow = outb + ((size_t)(n * CH + co)) * HW;
#pragma unroll
        for (int n8 = 0; n8 < 8; n8++) {
            const int pixl = pix0 + warp_n * 64 + n8 * 8 + tig * 2;
            *(float2*)(orow + pixl)            = make_float2(c[m][n8][0], c[m][n8][1]);
            *(float2*)(orow + (size_t)8 * HW + pixl) = make_float2(c[m][n8][2], c[m][n8][3]);
        }
    }
}

// ============================================================
// Kernel 2a/2b: GroupNorm stats, two-phase.
// ============================================================
__global__ __launch_bounds__(256) void gn_partA_kernel()
{
    const int id = blockIdx.x;               // ((head*8+b)*8+g)*16+slice
    const int head = id >> 10;
    const int b = (id >> 7) & 7;
    const int g = (id >> 4) & 7;
    const int sl = id & 15;
    const float4* p4 = (const float4*)((head ? g_hs : g_hd)
                     + ((size_t)(b * CH + g * CPG)) * HW + sl * 32768);
    const int tid = threadIdx.x;
    float s = 0.f, s2 = 0.f;
    for (int i = tid; i < 8192; i += 256) {
        float4 v = p4[i];
        s += (v.x + v.y) + (v.z + v.w);
        s2 = fmaf(v.x, v.x, fmaf(v.y, v.y, fmaf(v.z, v.z, fmaf(v.w, v.w, s2))));
    }
    __shared__ float sh[256], sh2[256];
    sh[tid] = s; sh2[tid] = s2;
    __syncthreads();
    for (int off = 128; off > 0; off >>= 1) {
        if (tid < off) { sh[tid] += sh[tid + off]; sh2[tid] += sh2[tid + off]; }
        __syncthreads();
    }
    if (tid == 0) { g_part[id * 2] = sh[0]; g_part[id * 2 + 1] = sh2[0]; }
}

__global__ void gn_partB_kernel()
{
    const int t = threadIdx.x;
    if (t >= 128) return;
    float s = 0.f, s2 = 0.f;
    for (int i = 0; i < 16; i++) {
        s  += g_part[(t * 16 + i) * 2];
        s2 += g_part[(t * 16 + i) * 2 + 1];
    }
    const float mu = s / 524288.f;
    const float var = s2 / 524288.f - mu * mu;
    g_stats[t * 2] = mu;
    g_stats[t * 2 + 1] = rsqrtf(var + 1e-5f);
}

// ============================================================
// Kernel 3: per-pixel epilogue. GN affine + exact GELU + 1x1 convs
// + sigmoid/CORN decode/normalize/labels.
// ============================================================
__global__ __launch_bounds__(256) void epilogue_kernel(
    const float* __restrict__ dgs, const float* __restrict__ dgb,
    const float* __restrict__ dw2, const float* __restrict__ db2,
    const float* __restrict__ sgs, const float* __restrict__ sgb,
    const float* __restrict__ sw2, const float* __restrict__ sb2,
    float* __restrict__ out)
{
    __shared__ float s_dgs[CH], s_dgb[CH], s_dw2[CH];
    __shared__ float s_sgs[CH], s_sgb[CH], s_sw0[CH], s_sw1[CH];
    __shared__ float s_mu[2][NGRP], s_rs[2][NGRP];

    const int tid = threadIdx.x;
    const int p   = blockIdx.x * 256 + tid;
    const int n   = p >> 14;
    const int pix = p & 16383;

    for (int c = tid; c < CH; c += 256) {
        s_dgs[c] = dgs[c]; s_dgb[c] = dgb[c]; s_dw2[c] = dw2[c];
        s_sgs[c] = sgs[c]; s_sgb[c] = sgb[c];
        s_sw0[c] = sw2[c]; s_sw1[c] = sw2[CH + c];
    }
    if (tid < 16) {
        int h = tid >> 3, g = tid & 7;
        int idx = ((h * BATCH + n) * NGRP + g) * 2;
        s_mu[h][g] = g_stats[idx];
        s_rs[h][g] = g_stats[idx + 1];
    }
    __syncthreads();

    const float* hd = g_hd + (size_t)n * CH * HW + pix;
    const float* hs = g_hs + (size_t)n * CH * HW + pix;

    float dl = 0.f, sl0 = 0.f, sl1 = 0.f;
#pragma unroll 4
    for (int c = 0; c < CH; c++) {
        const int g = c >> 5;
        float v  = hd[(size_t)c * HW];
        float xn = fmaf((v - s_mu[0][g]) * s_rs[0][g], s_dgs[c], s_dgb[c]);
        float ge = xn * normcdff(xn);
        dl = fmaf(ge, s_dw2[c], dl);

        v  = hs[(size_t)c * HW];
        xn = fmaf((v - s_mu[1][g]) * s_rs[1][g], s_sgs[c], s_sgb[c]);
        ge = xn * normcdff(xn);
        sl0 = fmaf(ge, s_sw0[c], sl0);
        sl1 = fmaf(ge, s_sw1[c], sl1);
    }
    dl  += db2[0];
    sl0 += sb2[0];
    sl1 += sb2[1];

    const float pd = 1.f / (1.f + expf(-dl));
    const float t0 = 1.f / (1.f + expf(-sl0));
    const float t1 = t0 * (1.f / (1.f + expf(-sl1)));
    float sev0 = fmaxf(1.f - t0, 1e-8f);
    float sev1 = fmaxf(t0 - t1, 1e-8f);
    float sev2 = fmaxf(t1,       1e-8f);
    const float ssum = fmaxf(sev0 + sev1 + sev2, 1e-8f);
    sev0 /= ssum; sev1 /= ssum; sev2 /= ssum;

    float px0 = fmaxf(1.f - pd,   1e-8f);
    float px1 = fmaxf(pd * sev0,  1e-8f);
    float px2 = fmaxf(pd * sev1,  1e-8f);
    float px3 = fmaxf(pd * sev2,  1e-8f);
    const float psum = fmaxf(px0 + px1 + px2 + px3, 1e-8f);
    px0 /= psum; px1 /= psum; px2 /= psum; px3 /= psum;

    int sp = 0; float bm = sev0;
    if (sev1 > bm) { bm = sev1; sp = 1; }
    if (sev2 > bm) { bm = sev2; sp = 2; }
    const int lbl = (pd >= 0.5f) ? (sp + 1) : 0;

    out[O_DMG  + n * HW + pix]            = dl;
    out[O_CORN + (n * 2 + 0) * HW + pix]  = sl0;
    out[O_CORN + (n * 2 + 1) * HW + pix]  = sl1;
    out[O_PIX  + (n * 4 + 0) * HW + pix]  = px0;
    out[O_PIX  + (n * 4 + 1) * HW + pix]  = px1;
    out[O_PIX  + (n * 4 + 2) * HW + pix]  = px2;
    out[O_PIX  + (n * 4 + 3) * HW + pix]  = px3;
    out[O_PRED + n * HW + pix]            = (float)lbl;
}

// ============================================================
// Kernel 4: masked mean + exact top-k sum per (b,c). 32 blocks.
// ============================================================
__global__ __launch_bounds__(256) void reduce_topk_kernel(
    const float* __restrict__ mask, const float* __restrict__ pix)
{
    extern __shared__ unsigned skey[];
    __shared__ int   ibuf[256];
    __shared__ float fbuf[256];

    const int tid = threadIdx.x;
    const int b = blockIdx.x >> 2;
    const int c = blockIdx.x & 3;
    const float* pv = pix  + ((size_t)b * 4 + c) * HW;
    const float* mk = mask + (size_t)b * HW;

    for (int i = tid; i < HW; i += 256)
        skey[i] = (mk[i] > 0.5f) ? __float_as_uint(pv[i]) : 0u;
    __syncthreads();

    int   mc = 0;
    float ms = 0.f;
    for (int i = tid; i < HW; i += 256) {
        unsigned kk = skey[i];
        if (kk) { mc++; ms += __uint_as_float(kk); }
    }
    ibuf[tid] = mc; fbuf[tid] = ms;
    __syncthreads();
    for (int off = 128; off > 0; off >>= 1) {
        if (tid < off) { ibuf[tid] += ibuf[tid + off]; fbuf[tid] += fbuf[tid + off]; }
        __syncthreads();
    }
    const int   cnt    = ibuf[0];
    const float sumall = fbuf[0];
    __syncthreads();

    int k = (int)rintf((float)cnt * 0.2f);
    if (k < 1) k = 1;
    const int cmax = (cnt > 1) ? cnt : 1;
    if (k > cmax) k = cmax;

    unsigned prefix = 0u;
    for (int bit = 30; bit >= 0; bit--) {
        const unsigned cand = prefix | (1u << bit);
        int cl = 0;
        for (int i = tid; i < HW; i += 256)
            if (skey[i] >= cand) cl++;
        ibuf[tid] = cl;
        __syncthreads();
        for (int off = 128; off > 0; off >>= 1) {
            if (tid < off) ibuf[tid] += ibuf[tid + off];
            __syncthreads();
        }
        if (ibuf[0] >= k) prefix = cand;
        __syncthreads();
    }

    int   cg = 0;
    float sg = 0.f;
    for (int i = tid; i < HW; i += 256) {
        unsigned kk = skey[i];
        if (kk > prefix) { cg++; sg += __uint_as_float(kk); }
    }
    ibuf[tid] = cg; fbuf[tid] = sg;
    __syncthreads();
    for (int off = 128; off > 0; off >>= 1) {
        if (tid < off) { ibuf[tid] += ibuf[tid + off]; fbuf[tid] += fbuf[tid + off]; }
        __syncthreads();
    }
    if (tid == 0) {
        const float T = __uint_as_float(prefix);
        const float topsum = fbuf[0] + (float)(k - ibuf[0]) * T;
        g_mean_raw[b * 4 + c] = sumall / (float)((cnt > 1) ? cnt : 1);
        g_topk_raw[b * 4 + c] = topsum / (float)k;
        g_cnt[b] = cnt;
    }
}

// ============================================================
// Kernel 5: finalize
// ============================================================
__global__ void finalize_kernel(float* __restrict__ out)
{
    const int b = threadIdx.x;
    if (b >= BATCH) return;
    const int cnt = g_cnt[b];

    float m[4], t[4], a[4];
    float sm = 0.f, st = 0.f;
    for (int c = 0; c < 4; c++) {
        m[c] = (cnt == 0) ? 0.25f : fmaxf(g_mean_raw[b * 4 + c], 1e-8f);
        t[c] = (cnt == 0) ? 0.25f : fmaxf(g_topk_raw[b * 4 + c], 1e-8f);
        sm += m[c]; st += t[c];
    }
    sm = fmaxf(sm, 1e-8f); st = fmaxf(st, 1e-8f);
    float sa = 0.f;
    for (int c = 0; c < 4; c++) {
        m[c] /= sm; t[c] /= st;
        a[c] = fmaxf(0.7f * m[c] + 0.3f * t[c], 1e-8f);
        sa += a[c];
    }
    sa = fmaxf(sa, 1e-8f);
    int best = 0; float bv = -1.f;
    for (int c = 0; c < 4; c++) {
        a[c] /= sa;
        if (a[c] > bv) { bv = a[c]; best = c; }
        out[O_MEAN + b * 4 + c] = m[c];
        out[O_TOPK + b * 4 + c] = t[c];
        out[O_AGG  + b * 4 + c] = a[c];
    }
    out[O_AGGL + b] = (float)best;
}

// ============================================================
extern "C" void kernel_launch(void* const* d_in, const int* in_sizes, int n_in,
                              void* d_out, int out_size)
{
    const float* fm   = (const float*)d_in[0];
    const float* mask = (const float*)d_in[1];
    const float* dw1  = (const float*)d_in[2];
    const float* dgs  = (const float*)d_in[3];
    const float* dgb  = (const float*)d_in[4];
    const float* dw2  = (const float*)d_in[5];
    const float* db2  = (const float*)d_in[6];
    const float* sw1  = (const float*)d_in[7];
    const float* sgs  = (const float*)d_in[8];
    const float* sgb  = (const float*)d_in[9];
    const float* sw2  = (const float*)d_in[10];
    const float* sb2  = (const float*)d_in[11];
    float* out = (float*)d_out;

    cudaFuncSetAttribute(conv_tf32_kernel,
                         cudaFuncAttributeMaxDynamicSharedMemorySize, 2 * STAGE_BYTES);
    cudaFuncSetAttribute(reduce_topk_kernel,
                         cudaFuncAttributeMaxDynamicSharedMemorySize, HW * 4);

    convert_w_kernel<<<dim3(64, 9, 2), 256>>>(dw1, sw1);
    convert_in_kernel<<<dim3(8192, 8), 256>>>(fm);
    conv_tf32_kernel<<<dim3(4, 512), 256, 2 * STAGE_BYTES>>>();
    gn_partA_kernel<<<2048, 256>>>();
    gn_partB_kernel<<<1, 128>>>();
    epilogue_kernel<<<NPIX / 256, 256>>>(dgs, dgb, dw2, db2, sgs, sgb, sw2, sb2, out);
    reduce_topk_kernel<<<BATCH * 4, 256, HW * 4>>>(mask, out + O_PIX);
    finalize_kernel<<<1, 32>>>(out);
}

// round 7
// speedup vs baseline: 8.6667x; 1.8264x over previous
#include <cuda_runtime.h>
#include <cuda_fp16.h>
#include <math.h>
#include <stdint.h>

// Problem constants
#define BATCH 8
#define CIN   256
#define CH    256
#define HH    128
#define WW    128
#define HW    (HH*WW)          // 16384
#define NPIX  (BATCH*HW)       // 131072
#define NGRP  8
#define CPG   32

// Output layout (float32, tuple order, flattened+concatenated)
#define O_DMG   0
#define O_CORN  131072
#define O_PIX   393216
#define O_PRED  917504
#define O_MEAN  1048576
#define O_TOPK  1048608
#define O_AGG   1048640
#define O_AGGL  1048672

// -------- scratch (no cudaMalloc allowed) --------
__device__ float g_hd[(size_t)BATCH*CH*HW];          // damage conv3x3 out
__device__ float g_hs[(size_t)BATCH*CH*HW];          // severity conv3x3 out
// Weights, fp16 frag-permuted: [head][rs(9)][mg(16)][kk(16)][lane(32)] uint4 (a0..a3 half2)
__device__ uint4 g_wah[2*9*16*16*32];
__device__ uint4 g_wal[2*9*16*16*32];
// Input, fp16 frag-permuted, 3 x-shift planes: [s][n][pg(2048)][kk(16)][lane(32)] uint2 (b0,b1)
__device__ uint2 g_bah[(size_t)3*BATCH*2048*16*32];
__device__ uint2 g_bal[(size_t)3*BATCH*2048*16*32];
__device__ float g_part[2048*2];
__device__ float g_stats[2*BATCH*NGRP*2];
__device__ float g_mean_raw[BATCH*4];
__device__ float g_topk_raw[BATCH*4];
__device__ int   g_cnt[BATCH];

#define MMA_FP16(c, a, b) \
    asm volatile("mma.sync.aligned.m16n8k16.row.col.f32.f16.f16.f32 " \
        "{%0,%1,%2,%3},{%4,%5,%6,%7},{%8,%9},{%0,%1,%2,%3};" \
        : "+f"((c)[0]), "+f"((c)[1]), "+f"((c)[2]), "+f"((c)[3]) \
        : "r"((a).x), "r"((a).y), "r"((a).z), "r"((a).w), "r"((b).x), "r"((b).y))

#define CP_ASYNC16(dst, src) \
    asm volatile("cp.async.cg.shared.global [%0], [%1], 16;" :: "r"(dst), "l"(src) : "memory")
#define CP_ASYNC16P(dst, src, sz) \
    asm volatile("cp.async.cg.shared.global [%0], [%1], 16, %2;" :: "r"(dst), "l"(src), "r"(sz) : "memory")
#define CP_COMMIT()  asm volatile("cp.async.commit_group;" ::: "memory")
#define CP_WAIT1()   asm volatile("cp.async.wait_group 1;" ::: "memory")

__device__ __forceinline__ uint32_t pack_h2(float a, float b) {
    __half2 h = __halves2half2(__float2half_rn(a), __float2half_rn(b));
    return *reinterpret_cast<uint32_t*>(&h);
}

// ============================================================
// Kernel 0a: weight split into fp16 hi/lo, m16n8k16 frag-permuted.
// grid = (32, 9, 2), 256 thr.
// a0 = (co row g,   ci 2tig..+1)   a1 = (row g+8, same ci)
// a2 = (row g,      ci 2tig+8..+9) a3 = (row g+8, same)
// ============================================================
__global__ __launch_bounds__(256) void convert_w_kernel(
    const float* __restrict__ dw1, const float* __restrict__ sw1)
{
    const int i = blockIdx.x * 256 + threadIdx.x;    // 0..8191
    const int mg = i >> 9;                           // 0..15
    const int kk = (i >> 5) & 15;                    // 0..15
    const int l  = i & 31;
    const int g = l >> 2, tig = l & 3;
    const int head = blockIdx.z, rs = blockIdx.y;
    const int r = rs / 3, s = rs - r * 3;
    const float* w = head ? sw1 : dw1;

    const int co0 = mg * 16 + g;
    const int ciA = kk * 16 + 2 * tig;
    const int ciB = ciA + 8;

    float v[8];
    const int cos[8]  = {co0, co0, co0 + 8, co0 + 8, co0, co0, co0 + 8, co0 + 8};
    const int cis[8]  = {ciA, ciA + 1, ciA, ciA + 1, ciB, ciB + 1, ciB, ciB + 1};
#pragma unroll
    for (int q = 0; q < 8; q++)
        v[q] = w[((cos[q] * CIN + cis[q]) * 3 + r) * 3 + s];

    float h[8], lo[8];
#pragma unroll
    for (int q = 0; q < 8; q++) {
        h[q]  = __half2float(__float2half_rn(v[q]));
        lo[q] = v[q] - h[q];
    }
    uint4 hi4, lo4;
    hi4.x = pack_h2(h[0], h[1]);  lo4.x = pack_h2(lo[0], lo[1]);
    hi4.y = pack_h2(h[2], h[3]);  lo4.y = pack_h2(lo[2], lo[3]);
    hi4.z = pack_h2(h[4], h[5]);  lo4.z = pack_h2(lo[4], lo[5]);
    hi4.w = pack_h2(h[6], h[7]);  lo4.w = pack_h2(lo[6], lo[7]);
    const size_t off = (((size_t)(head * 9 + rs) * 16 + mg) * 16 + kk) * 32 + l;
    g_wah[off] = hi4;
    g_wal[off] = lo4;
}

// ============================================================
// Kernel 0b: input split into fp16 hi/lo, frag-permuted,
// 3 pre-applied x-shifts (zeros at x edges). grid = (4096, 8).
// b0 = (ci 2tig..+1, pixel pg*8+g), b1 = (ci 2tig+8..+9, same pixel)
// ============================================================
__global__ __launch_bounds__(256) void convert_in_kernel(const float* __restrict__ in)
{
    const int n = blockIdx.y;
    const int i = blockIdx.x * 256 + threadIdx.x;    // 0..1048575
    const int pg = i >> 9;                           // 0..2047
    const int kk = (i >> 5) & 15;
    const int l  = i & 31;
    const int g = l >> 2, tig = l & 3;
    const int pix = pg * 8 + g;
    const int x = pix & 127;
    const int ciA = kk * 16 + 2 * tig;

    float v[4][3];
    const int cs[4] = {ciA, ciA + 1, ciA + 8, ciA + 9};
#pragma unroll
    for (int q = 0; q < 4; q++) {
        const float* p = in + ((size_t)(n * CIN + cs[q])) * HW + pix;
        v[q][0] = (x > 0)   ? p[-1] : 0.f;
        v[q][1] = p[0];
        v[q][2] = (x < 127) ? p[1]  : 0.f;
    }
#pragma unroll
    for (int s = 0; s < 3; s++) {
        float h[4], lo[4];
#pragma unroll
        for (int q = 0; q < 4; q++) {
            h[q]  = __half2float(__float2half_rn(v[q][s]));
            lo[q] = v[q][s] - h[q];
        }
        uint2 hi2, lo2;
        hi2.x = pack_h2(h[0], h[1]);  lo2.x = pack_h2(lo[0], lo[1]);
        hi2.y = pack_h2(h[2], h[3]);  lo2.y = pack_h2(lo[2], lo[3]);
        const size_t off = (((size_t)(s * BATCH + n) * 2048 + pg) * 16 + kk) * 32 + l;
        g_bah[off] = hi2;
        g_bal[off] = lo2;
    }
}

// ============================================================
// Kernel 1: conv3x3 via 3-term fp16-split m16n8k16 implicit GEMM.
// CTA = 128co x 256px, 8 warps (2m x 4n) of 64x64.
// 144 k16 steps (9 rs x 16 kk), stage = 4 kk (K=64), 36 stages,
// 2-stage cp.async pipeline. grid = dim3(4, 512).
// ============================================================
#define STAGE_BYTES 98304   // Ah 16K | Al 16K | Bh 32K | Bl 32K
#define A_LO_OFF 16384
#define B_HI_OFF 32768
#define B_LO_OFF 65536

__device__ __forceinline__ void stage_load(
    char* sp, int st, int head, int cotile, int sn_base, int pg0, int tid)
{
    const int rs  = st >> 2;
    const int kk0 = (st & 3) * 4;
    const int r = rs / 3, s = rs - r * 3;

    // A: 2048 uint4 (hi 1024 + lo 1024), 8 per thread
    const size_t abase = (((size_t)(head * 9 + rs) * 16 + cotile * 8) * 16 + kk0) * 32;
#pragma unroll
    for (int it = 0; it < 8; it++) {
        const int cid = tid + it * 256;
        const int prec = cid >> 10, cc = cid & 1023;
        const int mgl = cc >> 7, kkl = (cc >> 5) & 3, ll = cc & 31;
        const uint4* src = (prec ? g_wal : g_wah) + abase + mgl * 512 + kkl * 32 + ll;
        uint32_t dst = (uint32_t)__cvta_generic_to_shared(
            sp + prec * A_LO_OFF + ((mgl * 4 + kkl) * 32 + ll) * 16);
        CP_ASYNC16(dst, src);
    }
    // B: 4096 x 16B (hi+lo as lane-pairs), 16 per thread; row-shift predicate
    const size_t bbase = ((size_t)(s * BATCH + sn_base)) * 2048;
    const int pgsh = pg0 + (r - 1) * 16;
#pragma unroll
    for (int it = 0; it < 16; it++) {
        const int cid = tid + it * 256;
        const int prec = cid >> 11, cc = cid & 2047;
        const int pgl = cc >> 6, kkl = (cc >> 4) & 3, lp = cc & 15;
        const int pgsrc = pgsh + pgl;
        const unsigned ok = ((unsigned)pgsrc < 2048u);
        const int pgc = ok ? pgsrc : 0;
        const uint2* src = (prec ? g_bal : g_bah)
            + (((bbase + pgc) * 16 + kk0 + kkl) * 32 + lp * 2);
        uint32_t dst = (uint32_t)__cvta_generic_to_shared(
            sp + B_HI_OFF + prec * 32768 + ((pgl * 4 + kkl) * 32 + lp * 2) * 8);
        CP_ASYNC16P(dst, src, ok ? 16u : 0u);
    }
}

__global__ __launch_bounds__(256, 1) void conv_fp16_kernel()
{
    extern __shared__ char smem[];
    const int tid = threadIdx.x;
    const int lane = tid & 31;
    const int wid = tid >> 5;
    const int warp_m = wid >> 2;       // 0..1
    const int warp_n = wid & 3;        // 0..3
    const int g = lane >> 2, tig = lane & 3;

    const int head   = blockIdx.x >> 1;
    const int cotile = blockIdx.x & 1;
    const int ptile  = blockIdx.y;     // 0..511
    const int n      = ptile >> 6;
    const int pix0   = (ptile & 63) * 256;
    const int pg0    = (ptile & 63) * 32;

    float c[4][8][4];
#pragma unroll
    for (int m = 0; m < 4; m++)
#pragma unroll
        for (int nn = 0; nn < 8; nn++)
#pragma unroll
            for (int q = 0; q < 4; q++) c[m][nn][q] = 0.f;

    char* buf0 = smem;
    char* buf1 = smem + STAGE_BYTES;

    stage_load(buf0, 0, head, cotile, n, pg0, tid); CP_COMMIT();
    stage_load(buf1, 1, head, cotile, n, pg0, tid); CP_COMMIT();

    for (int st = 0; st < 36; st++) {
        CP_WAIT1();
        __syncthreads();
        char* sp = (st & 1) ? buf1 : buf0;

#pragma unroll
        for (int kkl = 0; kkl < 4; kkl++) {
            uint4 Ah[4], Al[4];
#pragma unroll
            for (int m = 0; m < 4; m++) {
                const int mgl = warp_m * 4 + m;
                Ah[m] = *(const uint4*)(sp + ((mgl * 4 + kkl) * 32 + lane) * 16);
                Al[m] = *(const uint4*)(sp + A_LO_OFF + ((mgl * 4 + kkl) * 32 + lane) * 16);
            }
#pragma unroll
            for (int n8 = 0; n8 < 8; n8++) {
                const int pgl = warp_n * 8 + n8;
                uint2 bh = *(const uint2*)(sp + B_HI_OFF + ((pgl * 4 + kkl) * 32 + lane) * 8);
                uint2 bl = *(const uint2*)(sp + B_LO_OFF + ((pgl * 4 + kkl) * 32 + lane) * 8);
#pragma unroll
                for (int m = 0; m < 4; m++) {
                    MMA_FP16(c[m][n8], Ah[m], bh);
                    MMA_FP16(c[m][n8], Al[m], bh);
                    MMA_FP16(c[m][n8], Ah[m], bl);
                }
            }
        }
        __syncthreads();
        if (st + 2 < 36)
            stage_load((st & 1) ? buf1 : buf0, st + 2, head, cotile, n, pg0, tid);
        CP_COMMIT();
    }

    // store to g_hd / g_hs [n][co][pix]
    float* outb = head ? g_hs : g_hd;
#pragma unroll
    for (int m = 0; m < 4; m++) {
        const int co = cotile * 128 + warp_m * 64 + m * 16 + g;
        float* orow = outb + ((size_t)(n * CH + co)) * HW;
#pragma unroll
        for (int n8 = 0; n8 < 8; n8++) {
            const int pixl = pix0 + warp_n * 64 + n8 * 8 + tig * 2;
            *(float2*)(orow + pixl)                  = make_float2(c[m][n8][0], c[m][n8][1]);
            *(float2*)(orow + (size_t)8 * HW + pixl) = make_float2(c[m][n8][2], c[m][n8][3]);
        }
    }
}

// ============================================================
// Kernel 2a/2b: GroupNorm stats, two-phase.
// ============================================================
__global__ __launch_bounds__(256) void gn_partA_kernel()
{
    const int id = blockIdx.x;               // ((head*8+b)*8+g)*16+slice
    const int head = id >> 10;
    const int b = (id >> 7) & 7;
    const int g = (id >> 4) & 7;
    const int sl = id & 15;
    const float4* p4 = (const float4*)((head ? g_hs : g_hd)
                     + ((size_t)(b * CH + g * CPG)) * HW + sl * 32768);
    const int tid = threadIdx.x;
    float s = 0.f, s2 = 0.f;
    for (int i = tid; i < 8192; i += 256) {
        float4 v = p4[i];
        s += (v.x + v.y) + (v.z + v.w);
        s2 = fmaf(v.x, v.x, fmaf(v.y, v.y, fmaf(v.z, v.z, fmaf(v.w, v.w, s2))));
    }
    __shared__ float sh[256], sh2[256];
    sh[tid] = s; sh2[tid] = s2;
    __syncthreads();
    for (int off = 128; off > 0; off >>= 1) {
        if (tid < off) { sh[tid] += sh[tid + off]; sh2[tid] += sh2[tid + off]; }
        __syncthreads();
    }
    if (tid == 0) { g_part[id * 2] = sh[0]; g_part[id * 2 + 1] = sh2[0]; }
}

__global__ void gn_partB_kernel()
{
    const int t = threadIdx.x;
    if (t >= 128) return;
    float s = 0.f, s2 = 0.f;
    for (int i = 0; i < 16; i++) {
        s  += g_part[(t * 16 + i) * 2];
        s2 += g_part[(t * 16 + i) * 2 + 1];
    }
    const float mu = s / 524288.f;
    const float var = s2 / 524288.f - mu * mu;
    g_stats[t * 2] = mu;
    g_stats[t * 2 + 1] = rsqrtf(var + 1e-5f);
}

// ============================================================
// Kernel 3: per-pixel epilogue. GN affine + exact GELU + 1x1 convs
// + sigmoid/CORN decode/normalize/labels.
// ============================================================
__global__ __launch_bounds__(256) void epilogue_kernel(
    const float* __restrict__ dgs, const float* __restrict__ dgb,
    const float* __restrict__ dw2, const float* __restrict__ db2,
    const float* __restrict__ sgs, const float* __restrict__ sgb,
    const float* __restrict__ sw2, const float* __restrict__ sb2,
    float* __restrict__ out)
{
    __shared__ float s_dgs[CH], s_dgb[CH], s_dw2[CH];
    __shared__ float s_sgs[CH], s_sgb[CH], s_sw0[CH], s_sw1[CH];
    __shared__ float s_mu[2][NGRP], s_rs[2][NGRP];

    const int tid = threadIdx.x;
    const int p   = blockIdx.x * 256 + tid;
    const int n   = p >> 14;
    const int pix = p & 16383;

    for (int c = tid; c < CH; c += 256) {
        s_dgs[c] = dgs[c]; s_dgb[c] = dgb[c]; s_dw2[c] = dw2[c];
        s_sgs[c] = sgs[c]; s_sgb[c] = sgb[c];
        s_sw0[c] = sw2[c]; s_sw1[c] = sw2[CH + c];
    }
    if (tid < 16) {
        int h = tid >> 3, g = tid & 7;
        int idx = ((h * BATCH + n) * NGRP + g) * 2;
        s_mu[h][g] = g_stats[idx];
        s_rs[h][g] = g_stats[idx + 1];
    }
    __syncthreads();

    const float* hd = g_hd + (size_t)n * CH * HW + pix;
    const float* hs = g_hs + (size_t)n * CH * HW + pix;

    float dl = 0.f, sl0 = 0.f, sl1 = 0.f;
#pragma unroll 4
    for (int c = 0; c < CH; c++) {
        const int g = c >> 5;
        float v  = hd[(size_t)c * HW];
        float xn = fmaf((v - s_mu[0][g]) * s_rs[0][g], s_dgs[c], s_dgb[c]);
        float ge = xn * normcdff(xn);
        dl = fmaf(ge, s_dw2[c], dl);

        v  = hs[(size_t)c * HW];
        xn = fmaf((v - s_mu[1][g]) * s_rs[1][g], s_sgs[c], s_sgb[c]);
        ge = xn * normcdff(xn);
        sl0 = fmaf(ge, s_sw0[c], sl0);
        sl1 = fmaf(ge, s_sw1[c], sl1);
    }
    dl  += db2[0];
    sl0 += sb2[0];
    sl1 += sb2[1];

    const float pd = 1.f / (1.f + expf(-dl));
    const float t0 = 1.f / (1.f + expf(-sl0));
    const float t1 = t0 * (1.f / (1.f + expf(-sl1)));
    float sev0 = fmaxf(1.f - t0, 1e-8f);
    float sev1 = fmaxf(t0 - t1, 1e-8f);
    float sev2 = fmaxf(t1,       1e-8f);
    const float ssum = fmaxf(sev0 + sev1 + sev2, 1e-8f);
    sev0 /= ssum; sev1 /= ssum; sev2 /= ssum;

    float px0 = fmaxf(1.f - pd,   1e-8f);
    float px1 = fmaxf(pd * sev0,  1e-8f);
    float px2 = fmaxf(pd * sev1,  1e-8f);
    float px3 = fmaxf(pd * sev2,  1e-8f);
    const float psum = fmaxf(px0 + px1 + px2 + px3, 1e-8f);
    px0 /= psum; px1 /= psum; px2 /= psum; px3 /= psum;

    int sp = 0; float bm = sev0;
    if (sev1 > bm) { bm = sev1; sp = 1; }
    if (sev2 > bm) { bm = sev2; sp = 2; }
    const int lbl = (pd >= 0.5f) ? (sp + 1) : 0;

    out[O_DMG  + n * HW + pix]            = dl;
    out[O_CORN + (n * 2 + 0) * HW + pix]  = sl0;
    out[O_CORN + (n * 2 + 1) * HW + pix]  = sl1;
    out[O_PIX  + (n * 4 + 0) * HW + pix]  = px0;
    out[O_PIX  + (n * 4 + 1) * HW + pix]  = px1;
    out[O_PIX  + (n * 4 + 2) * HW + pix]  = px2;
    out[O_PIX  + (n * 4 + 3) * HW + pix]  = px3;
    out[O_PRED + n * HW + pix]            = (float)lbl;
}

// ============================================================
// Kernel 4: masked mean + exact top-k sum per (b,c). 32 blocks.
// ============================================================
__global__ __launch_bounds__(256) void reduce_topk_kernel(
    const float* __restrict__ mask, const float* __restrict__ pix)
{
    extern __shared__ unsigned skey[];
    __shared__ int   ibuf[256];
    __shared__ float fbuf[256];

    const int tid = threadIdx.x;
    const int b = blockIdx.x >> 2;
    const int c = blockIdx.x & 3;
    const float* pv = pix  + ((size_t)b * 4 + c) * HW;
    const float* mk = mask + (size_t)b * HW;

    for (int i = tid; i < HW; i += 256)
        skey[i] = (mk[i] > 0.5f) ? __float_as_uint(pv[i]) : 0u;
    __syncthreads();

    int   mc = 0;
    float ms = 0.f;
    for (int i = tid; i < HW; i += 256) {
        unsigned kk = skey[i];
        if (kk) { mc++; ms += __uint_as_float(kk); }
    }
    ibuf[tid] = mc; fbuf[tid] = ms;
    __syncthreads();
    for (int off = 128; off > 0; off >>= 1) {
        if (tid < off) { ibuf[tid] += ibuf[tid + off]; fbuf[tid] += fbuf[tid + off]; }
        __syncthreads();
    }
    const int   cnt    = ibuf[0];
    const float sumall = fbuf[0];
    __syncthreads();

    int k = (int)rintf((float)cnt * 0.2f);
    if (k < 1) k = 1;
    const int cmax = (cnt > 1) ? cnt : 1;
    if (k > cmax) k = cmax;

    unsigned prefix = 0u;
    for (int bit = 30; bit >= 0; bit--) {
        const unsigned cand = prefix | (1u << bit);
        int cl = 0;
        for (int i = tid; i < HW; i += 256)
            if (skey[i] >= cand) cl++;
        ibuf[tid] = cl;
        __syncthreads();
        for (int off = 128; off > 0; off >>= 1) {
            if (tid < off) ibuf[tid] += ibuf[tid + off];
            __syncthreads();
        }
        if (ibuf[0] >= k) prefix = cand;
        __syncthreads();
    }

    int   cg = 0;
    float sg = 0.f;
    for (int i = tid; i < HW; i += 256) {
        unsigned kk = skey[i];
        if (kk > prefix) { cg++; sg += __uint_as_float(kk); }
    }
    ibuf[tid] = cg; fbuf[tid] = sg;
    __syncthreads();
    for (int off = 128; off > 0; off >>= 1) {
        if (tid < off) { ibuf[tid] += ibuf[tid + off]; fbuf[tid] += fbuf[tid + off]; }
        __syncthreads();
    }
    if (tid == 0) {
        const float T = __uint_as_float(prefix);
        const float topsum = fbuf[0] + (float)(k - ibuf[0]) * T;
        g_mean_raw[b * 4 + c] = sumall / (float)((cnt > 1) ? cnt : 1);
        g_topk_raw[b * 4 + c] = topsum / (float)k;
        g_cnt[b] = cnt;
    }
}

// ============================================================
// Kernel 5: finalize
// ============================================================
__global__ void finalize_kernel(float* __restrict__ out)
{
    const int b = threadIdx.x;
    if (b >= BATCH) return;
    const int cnt = g_cnt[b];

    float m[4], t[4], a[4];
    float sm = 0.f, st = 0.f;
    for (int c = 0; c < 4; c++) {
        m[c] = (cnt == 0) ? 0.25f : fmaxf(g_mean_raw[b * 4 + c], 1e-8f);
        t[c] = (cnt == 0) ? 0.25f : fmaxf(g_topk_raw[b * 4 + c], 1e-8f);
        sm += m[c]; st += t[c];
    }
    sm = fmaxf(sm, 1e-8f); st = fmaxf(st, 1e-8f);
    float sa = 0.f;
    for (int c = 0; c < 4; c++) {
        m[c] /= sm; t[c] /= st;
        a[c] = fmaxf(0.7f * m[c] + 0.3f * t[c], 1e-8f);
        sa += a[c];
    }
    sa = fmaxf(sa, 1e-8f);
    int best = 0; float bv = -1.f;
    for (int c = 0; c < 4; c++) {
        a[c] /= sa;
        if (a[c] > bv) { bv = a[c]; best = c; }
        out[O_MEAN + b * 4 + c] = m[c];
        out[O_TOPK + b * 4 + c] = t[c];
        out[O_AGG  + b * 4 + c] = a[c];
    }
    out[O_AGGL + b] = (float)best;
}

// ============================================================
extern "C" void kernel_launch(void* const* d_in, const int* in_sizes, int n_in,
                              void* d_out, int out_size)
{
    const float* fm   = (const float*)d_in[0];
    const float* mask = (const float*)d_in[1];
    const float* dw1  = (const float*)d_in[2];
    const float* dgs  = (const float*)d_in[3];
    const float* dgb  = (const float*)d_in[4];
    const float* dw2  = (const float*)d_in[5];
    const float* db2  = (const float*)d_in[6];
    const float* sw1  = (const float*)d_in[7];
    const float* sgs  = (const float*)d_in[8];
    const float* sgb  = (const float*)d_in[9];
    const float* sw2  = (const float*)d_in[10];
    const float* sb2  = (const float*)d_in[11];
    float* out = (float*)d_out;

    cudaFuncSetAttribute(conv_fp16_kernel,
                         cudaFuncAttributeMaxDynamicSharedMemorySize, 2 * STAGE_BYTES);
    cudaFuncSetAttribute(reduce_topk_kernel,
                         cudaFuncAttributeMaxDynamicSharedMemorySize, HW * 4);

    convert_w_kernel<<<dim3(32, 9, 2), 256>>>(dw1, sw1);
    convert_in_kernel<<<dim3(4096, 8), 256>>>(fm);
    conv_fp16_kernel<<<dim3(4, 512), 256, 2 * STAGE_BYTES>>>();
    gn_partA_kernel<<<2048, 256>>>();
    gn_partB_kernel<<<1, 128>>>();
    epilogue_kernel<<<NPIX / 256, 256>>>(dgs, dgb, dw2, db2, sgs, sgb, sw2, sb2, out);
    reduce_topk_kernel<<<BATCH * 4, 256, HW * 4>>>(mask, out + O_PIX);
    finalize_kernel<<<1, 32>>>(out);
}